// round 13
// baseline (speedup 1.0000x reference)
#include <cuda_runtime.h>
#include <math.h>

#define Bz   32
#define Nn   512
#define LITD 64
#define SEMD 64
#define Hh   64
#define Ee   128
#define G3H  192
#define OUTD 64
#define MAXD 128

// ---------------- device scratch (static, no allocations) ----------------
__device__ float g_xp [2u*Bz*Nn*G3H];   // GRU input projections (b0 folded)
__device__ float g_chA[4u*Bz*Nn*Ee];    // chain states buffer A (g1F,g1R,g2F,g2R)
__device__ float g_chB[4u*Bz*Nn*Ee];    // chain states buffer B
__device__ float g_ghw[4u*Bz*Nn*Ee];    // wh @ W_g
__device__ float g_ah1[4u*Bz*Nn];
__device__ float g_ah2[4u*Bz*Nn];
__device__ short g_adj[4u*Bz*Nn*MAXD];  // padded neighbor lists
__device__ int   g_cnt[4u*Bz*Nn];
__device__ float g_emb[2u*Bz*OUTD];

// ---------------- adjacency builders (deterministic, coalesced) ----------
// fwd lists: for row i, the set {j : A[b,i,j]=1}, in ascending j order.
__global__ void k_build_fwd(const float* __restrict__ A1,
                            const float* __restrict__ A2)
{
    int g = blockIdx.z;
    const float* A = g ? A2 : A1;
    int b = blockIdx.y;
    int w = threadIdx.x >> 5, lane = threadIdx.x & 31;
    int row = blockIdx.x * 8 + w;
    int v = g * 2;                       // variant 0 / 2
    const float* Ar = A + ((size_t)b * Nn + row) * Nn;
    short* out = g_adj + (((size_t)v * Bz + b) * Nn + row) * MAXD;
    int cnt = 0;
    for (int j0 = 0; j0 < Nn; j0 += 32) {
        float val = Ar[j0 + lane];
        unsigned m = __ballot_sync(0xffffffffu, val > 0.5f);
        if (val > 0.5f) {
            int pos = cnt + __popc(m & ((1u << lane) - 1u));
            if (pos < MAXD) out[pos] = (short)(j0 + lane);
        }
        cnt += __popc(m);
    }
    if (lane == 0) g_cnt[((size_t)v * Bz + b) * Nn + row] = cnt < MAXD ? cnt : MAXD;
}

// rev lists: for column j, the set {i : A[b,i,j]=1}, ascending i (A^T rows).
__global__ void k_build_rev(const float* __restrict__ A1,
                            const float* __restrict__ A2)
{
    int g = blockIdx.z;
    const float* A = g ? A2 : A1;
    int b = blockIdx.y;
    int w = threadIdx.x >> 5, lane = threadIdx.x & 31;
    int j = (blockIdx.x * 8 + w) * 32 + lane;
    int v = g * 2 + 1;                   // variant 1 / 3
    const float* Ab = A + (size_t)b * Nn * Nn;
    short* out = g_adj + (((size_t)v * Bz + b) * Nn + j) * MAXD;
    int cnt = 0;
    for (int i = 0; i < Nn; i += 4) {
        float v0 = Ab[(size_t)(i + 0) * Nn + j];
        float v1 = Ab[(size_t)(i + 1) * Nn + j];
        float v2 = Ab[(size_t)(i + 2) * Nn + j];
        float v3 = Ab[(size_t)(i + 3) * Nn + j];
        if (v0 > 0.5f && cnt < MAXD) out[cnt++] = (short)(i + 0);
        if (v1 > 0.5f && cnt < MAXD) out[cnt++] = (short)(i + 1);
        if (v2 > 0.5f && cnt < MAXD) out[cnt++] = (short)(i + 2);
        if (v3 > 0.5f && cnt < MAXD) out[cnt++] = (short)(i + 3);
    }
    g_cnt[((size_t)v * Bz + b) * Nn + j] = cnt;
}

// ---------------- literal path: relu(lit @ Wl) -> chain cols [0,64) -------
__global__ void k_lit(const float* __restrict__ L1, const float* __restrict__ L2,
                      const float* __restrict__ Wl1, const float* __restrict__ Wl2)
{
    int g = blockIdx.z, b = blockIdx.y, n0 = blockIdx.x * 64;
    const float* L  = (g ? L2 : L1) + ((size_t)b * Nn + n0) * LITD;
    const float* Wl = g ? Wl2 : Wl1;
    __shared__ float ls[64 * 64];
    int tid = threadIdx.x;                       // 256
    for (int idx = tid; idx < 64 * 64; idx += 256) ls[idx] = L[idx];
    __syncthreads();
    int col = tid & 63, q = tid >> 6;            // q in 0..3
    for (int ngrp = q; ngrp < 8; ngrp += 4) {
        float acc[8];
#pragma unroll
        for (int nn = 0; nn < 8; nn++) acc[nn] = 0.f;
#pragma unroll 8
        for (int k = 0; k < 64; k++) {
            float kv = __ldg(&Wl[k * 64 + col]);
#pragma unroll
            for (int nn = 0; nn < 8; nn++)
                acc[nn] = fmaf(ls[(ngrp * 8 + nn) * 64 + k], kv, acc[nn]);
        }
#pragma unroll
        for (int nn = 0; nn < 8; nn++) {
            float r = fmaxf(acc[nn], 0.f);
            int node = n0 + ngrp * 8 + nn;
            g_chA[(((size_t)(2 * g)     * Bz + b) * Nn + node) * Ee + col] = r;
            g_chA[(((size_t)(2 * g + 1) * Bz + b) * Nn + node) * Ee + col] = r;
        }
    }
}

// ---------------- GRU input projection: xp = sem @ k + b0 ----------------
__global__ void k_xp(const float* __restrict__ S1, const float* __restrict__ S2,
                     const float* __restrict__ K1, const float* __restrict__ K2,
                     const float* __restrict__ B1, const float* __restrict__ B2)
{
    int g = blockIdx.z, b = blockIdx.y, n0 = blockIdx.x * 64;
    const float* S  = (g ? S2 : S1) + ((size_t)b * Nn + n0) * SEMD;
    const float* Wk = g ? K2 : K1;
    const float* bb = g ? B2 : B1;               // row 0 of [2,192]
    __shared__ float ss[64 * 64];
    int tid = threadIdx.x;                       // 192
    for (int idx = tid; idx < 64 * 64; idx += 192) ss[idx] = S[idx];
    __syncthreads();
    int col = tid;
    float b0 = bb[col];
    float* xp = g_xp + (((size_t)g * Bz + b) * Nn + n0) * G3H;
    for (int ngrp = 0; ngrp < 8; ngrp++) {
        float acc[8];
#pragma unroll
        for (int nn = 0; nn < 8; nn++) acc[nn] = b0;
#pragma unroll 8
        for (int k = 0; k < 64; k++) {
            float kv = __ldg(&Wk[k * G3H + col]);
#pragma unroll
            for (int nn = 0; nn < 8; nn++)
                acc[nn] = fmaf(ss[(ngrp * 8 + nn) * 64 + k], kv, acc[nn]);
        }
#pragma unroll
        for (int nn = 0; nn < 8; nn++)
            xp[(size_t)(ngrp * 8 + nn) * G3H + col] = acc[nn];
    }
}

// ---------------- GRU scan (sequential over 512 nodes) -------------------
__global__ void __launch_bounds__(192, 1)
k_gru(const float* __restrict__ rk1, const float* __restrict__ rk2,
      const float* __restrict__ gb1, const float* __restrict__ gb2)
{
    int g = blockIdx.x >> 5;
    int b = blockIdx.x & 31;
    const float* rk = g ? rk2 : rk1;
    const float* gb = g ? gb2 : gb1;
    __shared__ float sm[12288];                  // 48KB: stage rk, then reuse
    int tid = threadIdx.x;                       // 192
    for (int idx = tid; idx < 64 * G3H; idx += 192) sm[idx] = rk[idx];
    __syncthreads();
    float rkc[64];
#pragma unroll
    for (int i = 0; i < 64; i++) rkc[i] = sm[i * G3H + tid];
    __syncthreads();
    float* h_sh   = sm;          // [64]
    float* pre_sh = sm + 64;     // [128]
    float* rh_sh  = sm + 192;    // [64]
    float* xh_sh  = sm + 256;    // [64]
    if (tid < 64) h_sh[tid] = 0.f;
    float bb = gb[G3H + tid];                    // recurrent bias b[1]
    const float* xp = g_xp + ((size_t)g * Bz + b) * Nn * G3H;
    float* outF = g_chA + (((size_t)(2 * g)     * Bz + b) * Nn) * Ee;
    float* outR = g_chA + (((size_t)(2 * g + 1) * Bz + b) * Nn) * Ee;
    __syncthreads();
    float xnext = xp[tid];
    for (int t = 0; t < Nn; t++) {
        float xv = xnext;
        if (t + 1 < Nn) xnext = xp[(size_t)(t + 1) * G3H + tid];
        float a0 = 0.f, a1 = 0.f, a2 = 0.f, a3 = 0.f;
#pragma unroll
        for (int i = 0; i < 64; i += 4) {
            float4 h4 = *(const float4*)(h_sh + i);
            a0 = fmaf(h4.x, rkc[i + 0], a0);
            a1 = fmaf(h4.y, rkc[i + 1], a1);
            a2 = fmaf(h4.z, rkc[i + 2], a2);
            a3 = fmaf(h4.w, rkc[i + 3], a3);
        }
        float pre = (a0 + a1) + (a2 + a3) + bb;
        if (tid < 128) pre_sh[tid] = xv + pre;
        else { rh_sh[tid - 128] = pre; xh_sh[tid - 128] = xv; }
        __syncthreads();
        if (tid < 64) {
            float z = 1.f / (1.f + __expf(-pre_sh[tid]));
            float r = 1.f / (1.f + __expf(-pre_sh[64 + tid]));
            float ag = xh_sh[tid] + r * rh_sh[tid];
            ag = fminf(fmaxf(ag, -12.f), 12.f);
            float e2 = __expf(-2.f * ag);
            float hh = (1.f - e2) / (1.f + e2);
            float hn = z * h_sh[tid] + (1.f - z) * hh;
            h_sh[tid] = hn;
            float rl = fmaxf(hn, 0.f);
            outF[(size_t)t * Ee + 64 + tid] = rl;
            outR[(size_t)t * Ee + 64 + tid] = rl;
        }
        __syncthreads();
    }
}

// ---------------- per-step transform: ghw = wh @ W_g; ah1/ah2 ------------
__global__ void __launch_bounds__(256)
k_transform(int srcA, const float* __restrict__ Wg,
            const float* __restrict__ a1w, const float* __restrict__ a1b,
            const float* __restrict__ a2w, const float* __restrict__ a2b)
{
    const float* wh = srcA ? g_chA : g_chB;
    __shared__ float Wg_sh[64 * 128];            // 32KB (one K-half)
    __shared__ float wh_sh[32 * 128];            // 16KB
    int c = blockIdx.z, b = blockIdx.y, n0 = blockIdx.x * 32;
    size_t base = (((size_t)c * Bz + b) * Nn + n0) * Ee;
    int tid = threadIdx.x;
    for (int idx = tid; idx < 32 * 128; idx += 256) wh_sh[idx] = wh[base + idx];
    int ng = tid >> 5, cg = tid & 31;
    float acc[4][4];
#pragma unroll
    for (int i = 0; i < 4; i++)
#pragma unroll
        for (int j = 0; j < 4; j++) acc[i][j] = 0.f;

    for (int kh = 0; kh < 2; kh++) {
        __syncthreads();
        for (int idx = tid; idx < 64 * 128; idx += 256)
            Wg_sh[idx] = Wg[kh * 64 * 128 + idx];
        __syncthreads();
#pragma unroll 4
        for (int k = 0; k < 64; k++) {
            float4 w4 = *(const float4*)(Wg_sh + k * 128 + cg * 4);
            int kk = kh * 64 + k;
#pragma unroll
            for (int nn = 0; nn < 4; nn++) {
                float w = wh_sh[(ng * 4 + nn) * 128 + kk];
                acc[nn][0] = fmaf(w, w4.x, acc[nn][0]);
                acc[nn][1] = fmaf(w, w4.y, acc[nn][1]);
                acc[nn][2] = fmaf(w, w4.z, acc[nn][2]);
                acc[nn][3] = fmaf(w, w4.w, acc[nn][3]);
            }
        }
    }
    float* ghp = g_ghw + base;
#pragma unroll
    for (int nn = 0; nn < 4; nn++) {
        float4 o = make_float4(acc[nn][0], acc[nn][1], acc[nn][2], acc[nn][3]);
        *(float4*)(ghp + (ng * 4 + nn) * 128 + cg * 4) = o;
    }
    // attention projections ah1/ah2 for this block's 32 nodes
    __syncthreads();
    if (tid < 128) Wg_sh[tid] = a1w[tid];
    else if (tid < 256) Wg_sh[tid] = a2w[tid - 128];
    __syncthreads();
    {
        int w = tid >> 5, lane = tid & 31;
#pragma unroll
        for (int nn = 0; nn < 4; nn++) {
            int node = w * 4 + nn;
            float x0 = wh_sh[node * 128 + lane];
            float x1 = wh_sh[node * 128 + 64 + lane];
            float s1 = x0 * Wg_sh[lane]       + x1 * Wg_sh[64 + lane];
            float s2 = x0 * Wg_sh[128 + lane] + x1 * Wg_sh[192 + lane];
#pragma unroll
            for (int off = 16; off; off >>= 1) {
                s1 += __shfl_xor_sync(0xffffffffu, s1, off);
                s2 += __shfl_xor_sync(0xffffffffu, s2, off);
            }
            if (lane == 0) {
                size_t idx = ((size_t)c * Bz + b) * Nn + n0 + node;
                g_ah1[idx] = s1 + a1b[0];
                g_ah2[idx] = s2 + a2b[0];
            }
        }
    }
}

// ---------------- per-step sparse attend + residual + elu ----------------
__global__ void __launch_bounds__(128)
k_attend(int srcA)
{
    const float* whc = srcA ? g_chA : g_chB;
    float*       whn = srcA ? g_chB : g_chA;
    int c = blockIdx.z, b = blockIdx.y, nb = blockIdx.x * 64;
    int tid = threadIdx.x, lane = tid & 31, w = tid >> 5;
    __shared__ float p_sh[MAXD];
    __shared__ short nj_sh[MAXD];
    __shared__ float red[8];
    size_t cb = ((size_t)c * Bz + b) * Nn;
    const float* ghw = g_ghw + cb * Ee;

    for (int ii = 0; ii < 64; ii++) {
        int i = nb + ii;
        int cnt = g_cnt[cb + i];
        float ah1i = g_ah1[cb + i];
        float e = -3.0e38f;
        if (tid < cnt) {
            short nj = g_adj[(cb + i) * MAXD + tid];
            float x = ah1i + g_ah2[cb + nj];
            e = x > 0.f ? x : 0.2f * x;          // leaky_relu 0.2
            nj_sh[tid] = nj;
        }
        float m = e;
#pragma unroll
        for (int off = 16; off; off >>= 1)
            m = fmaxf(m, __shfl_xor_sync(0xffffffffu, m, off));
        if (lane == 0) red[w] = m;
        __syncthreads();
        m = fmaxf(fmaxf(red[0], red[1]), fmaxf(red[2], red[3]));
        float p = (tid < cnt) ? __expf(e - m) : 0.f;
        float s = p;
#pragma unroll
        for (int off = 16; off; off >>= 1)
            s += __shfl_xor_sync(0xffffffffu, s, off);
        if (lane == 0) red[4 + w] = s;
        __syncthreads();
        s = (red[4] + red[5]) + (red[6] + red[7]);
        float inv = cnt > 0 ? 1.f / s : 0.f;
        p_sh[tid] = p * inv;
        __syncthreads();
        float acc0 = 0.f, acc1 = 0.f;
        int j = 0;
        for (; j + 1 < cnt; j += 2) {
            acc0 = fmaf(p_sh[j],     ghw[(size_t)nj_sh[j]     * Ee + tid], acc0);
            acc1 = fmaf(p_sh[j + 1], ghw[(size_t)nj_sh[j + 1] * Ee + tid], acc1);
        }
        if (j < cnt)
            acc0 = fmaf(p_sh[j], ghw[(size_t)nj_sh[j] * Ee + tid], acc0);
        float v = whc[(cb + i) * Ee + tid] + (acc0 + acc1);
        whn[(cb + i) * Ee + tid] = v > 0.f ? v : expm1f(v);   // elu
        __syncthreads();
    }
}

// ---------------- sum over nodes + output projection ---------------------
__global__ void k_reduce(const float* __restrict__ Wout,
                         const float* __restrict__ bout)
{
    int b = blockIdx.x, g = blockIdx.y;
    int tid = threadIdx.x;                       // 128
    __shared__ float mid[128];
    const float* f = g_chB + ((size_t)(2 * g)     * Bz + b) * Nn * Ee;
    const float* r = g_chB + ((size_t)(2 * g + 1) * Bz + b) * Nn * Ee;
    float s = 0.f;
#pragma unroll 4
    for (int n = 0; n < Nn; n++)
        s += f[(size_t)n * Ee + tid] + r[(size_t)n * Ee + tid];
    mid[tid] = s;
    __syncthreads();
    if (tid < OUTD) {
        float acc = bout[tid];
#pragma unroll 8
        for (int e = 0; e < Ee; e++)
            acc = fmaf(mid[e], __ldg(&Wout[e * OUTD + tid]), acc);
        g_emb[((size_t)g * Bz + b) * OUTD + tid] = acc;
    }
}

// ---------------- cosine similarity -> (1+cos)/2 -------------------------
__global__ void k_cos(float* __restrict__ out)
{
    int b = blockIdx.x;
    int tid = threadIdx.x, lane = tid & 31, w = tid >> 5;   // 64 threads
    float x1 = g_emb[(size_t)b * OUTD + tid];
    float x2 = g_emb[(size_t)(Bz + b) * OUTD + tid];
    float d = x1 * x2, n1 = x1 * x1, n2 = x2 * x2;
#pragma unroll
    for (int off = 16; off; off >>= 1) {
        d  += __shfl_xor_sync(0xffffffffu, d,  off);
        n1 += __shfl_xor_sync(0xffffffffu, n1, off);
        n2 += __shfl_xor_sync(0xffffffffu, n2, off);
    }
    __shared__ float sh[6];
    if (lane == 0) { sh[w * 3] = d; sh[w * 3 + 1] = n1; sh[w * 3 + 2] = n2; }
    __syncthreads();
    if (tid == 0) {
        float dd = sh[0] + sh[3], a = sh[1] + sh[4], c2 = sh[2] + sh[5];
        float denom = fmaxf(sqrtf(a), 1e-12f) * fmaxf(sqrtf(c2), 1e-12f);
        out[b] = 0.5f * (1.f + dd / denom);
    }
}

// ---------------- launch sequence ----------------------------------------
extern "C" void kernel_launch(void* const* d_in, const int* in_sizes, int n_in,
                              void* d_out, int out_size)
{
    const float* CFG1 = (const float*)d_in[0];
    const float* LIT1 = (const float*)d_in[2];
    const float* SEM1 = (const float*)d_in[3];
    const float* CFG2 = (const float*)d_in[4];
    const float* LIT2 = (const float*)d_in[6];
    const float* SEM2 = (const float*)d_in[7];
    const float* Wl1  = (const float*)d_in[8];
    const float* gk1  = (const float*)d_in[9];
    const float* grk1 = (const float*)d_in[10];
    const float* gb1  = (const float*)d_in[11];
    const float* Wl2  = (const float*)d_in[12];
    const float* gk2  = (const float*)d_in[13];
    const float* grk2 = (const float*)d_in[14];
    const float* gb2  = (const float*)d_in[15];
    const float* a1w  = (const float*)d_in[16];
    const float* a1b  = (const float*)d_in[17];
    const float* a2w  = (const float*)d_in[18];
    const float* a2b  = (const float*)d_in[19];
    const float* Wg   = (const float*)d_in[20];
    const float* Wout = (const float*)d_in[21];
    const float* bout = (const float*)d_in[22];

    k_build_fwd<<<dim3(64, 32, 2), 256>>>(CFG1, CFG2);
    k_build_rev<<<dim3(2, 32, 2), 256>>>(CFG1, CFG2);
    k_lit<<<dim3(8, 32, 2), 256>>>(LIT1, LIT2, Wl1, Wl2);
    k_xp <<<dim3(8, 32, 2), 192>>>(SEM1, SEM2, gk1, gk2, gb1, gb2);
    k_gru<<<64, 192>>>(grk1, grk2, gb1, gb2);

    int srcA = 1;
    for (int s = 0; s < 3; s++) {
        k_transform<<<dim3(16, 32, 4), 256>>>(srcA, Wg, a1w, a1b, a2w, a2b);
        k_attend   <<<dim3(8, 32, 4), 128>>>(srcA);
        srcA ^= 1;
    }
    // after 3 steps, final states are in g_chB
    k_reduce<<<dim3(32, 2), 128>>>(Wout, bout);
    k_cos<<<32, 64>>>((float*)d_out);
}

// round 14
// speedup vs baseline: 1.3070x; 1.3070x over previous
#include <cuda_runtime.h>
#include <cuda_fp16.h>
#include <math.h>

#define Bz   32
#define Nn   512
#define LITD 64
#define SEMD 64
#define Hh   64
#define Ee   128
#define G3H  192
#define OUTD 64
#define MAXD 128

typedef unsigned long long ull;

// ---------------- packed fp32x2 helpers ----------------------------------
__device__ __forceinline__ ull pk2(float x, float y) {
    union { float2 f; ull u; } t; t.f = make_float2(x, y); return t.u;
}
__device__ __forceinline__ float2 upk2(ull u) {
    union { float2 f; ull u; } t; t.u = u; return t.f;
}
__device__ __forceinline__ void ffma2(ull& d, ull a, ull b) {
    asm("fma.rn.f32x2 %0, %1, %2, %0;" : "+l"(d) : "l"(a), "l"(b));
}

// ---------------- device scratch (static, no allocations) ----------------
__device__ float  g_xp [2u*Bz*Nn*G3H];
__device__ float  g_chA[4u*Bz*Nn*Ee];
__device__ float  g_chB[4u*Bz*Nn*Ee];
__device__ __half g_ghwh[4u*Bz*Nn*Ee];  // wh @ W_g in fp16
__device__ float  g_ah1[4u*Bz*Nn];
__device__ float  g_ah2[4u*Bz*Nn];
__device__ short  g_adj[4u*Bz*Nn*MAXD];
__device__ int    g_cnt[4u*Bz*Nn];
__device__ float  g_emb[2u*Bz*OUTD];

// ---------------- adjacency builders -------------------------------------
__global__ void k_build_fwd(const float* __restrict__ A1,
                            const float* __restrict__ A2)
{
    int g = blockIdx.z;
    const float* A = g ? A2 : A1;
    int b = blockIdx.y;
    int w = threadIdx.x >> 5, lane = threadIdx.x & 31;
    int row = blockIdx.x * 8 + w;
    int v = g * 2;
    const float* Ar = A + ((size_t)b * Nn + row) * Nn;
    short* out = g_adj + (((size_t)v * Bz + b) * Nn + row) * MAXD;
    int cnt = 0;
    for (int j0 = 0; j0 < Nn; j0 += 32) {
        float val = Ar[j0 + lane];
        unsigned m = __ballot_sync(0xffffffffu, val > 0.5f);
        if (val > 0.5f) {
            int pos = cnt + __popc(m & ((1u << lane) - 1u));
            if (pos < MAXD) out[pos] = (short)(j0 + lane);
        }
        cnt += __popc(m);
    }
    if (lane == 0) g_cnt[((size_t)v * Bz + b) * Nn + row] = cnt < MAXD ? cnt : MAXD;
}

__global__ void k_build_rev(const float* __restrict__ A1,
                            const float* __restrict__ A2)
{
    int g = blockIdx.z;
    const float* A = g ? A2 : A1;
    int b = blockIdx.y;
    int w = threadIdx.x >> 5, lane = threadIdx.x & 31;
    int j = (blockIdx.x * 8 + w) * 32 + lane;
    int v = g * 2 + 1;
    const float* Ab = A + (size_t)b * Nn * Nn;
    short* out = g_adj + (((size_t)v * Bz + b) * Nn + j) * MAXD;
    int cnt = 0;
    for (int i = 0; i < Nn; i += 4) {
        float v0 = Ab[(size_t)(i + 0) * Nn + j];
        float v1 = Ab[(size_t)(i + 1) * Nn + j];
        float v2 = Ab[(size_t)(i + 2) * Nn + j];
        float v3 = Ab[(size_t)(i + 3) * Nn + j];
        if (v0 > 0.5f && cnt < MAXD) out[cnt++] = (short)(i + 0);
        if (v1 > 0.5f && cnt < MAXD) out[cnt++] = (short)(i + 1);
        if (v2 > 0.5f && cnt < MAXD) out[cnt++] = (short)(i + 2);
        if (v3 > 0.5f && cnt < MAXD) out[cnt++] = (short)(i + 3);
    }
    g_cnt[((size_t)v * Bz + b) * Nn + j] = cnt;
}

// ---------------- literal path: relu(lit @ Wl) ---------------------------
__global__ void k_lit(const float* __restrict__ L1, const float* __restrict__ L2,
                      const float* __restrict__ Wl1, const float* __restrict__ Wl2)
{
    int g = blockIdx.z, b = blockIdx.y, n0 = blockIdx.x * 64;
    const float* L  = (g ? L2 : L1) + ((size_t)b * Nn + n0) * LITD;
    const float* Wl = g ? Wl2 : Wl1;
    __shared__ __align__(16) float ls[64 * 64];
    int tid = threadIdx.x;                       // 256
    for (int idx = tid; idx < 64 * 64; idx += 256) ls[idx] = L[idx];
    int col = tid & 63, q = tid >> 6;
    ull wl2[32];
#pragma unroll
    for (int i = 0; i < 32; i++)
        wl2[i] = pk2(__ldg(&Wl[(2 * i) * 64 + col]), __ldg(&Wl[(2 * i + 1) * 64 + col]));
    __syncthreads();
    for (int ngrp = q; ngrp < 8; ngrp += 4) {
        ull acc[8];
#pragma unroll
        for (int nn = 0; nn < 8; nn++) acc[nn] = pk2(0.f, 0.f);
#pragma unroll
        for (int kq = 0; kq < 32; kq++) {
#pragma unroll
            for (int nn = 0; nn < 8; nn++)
                ffma2(acc[nn], *(const ull*)(ls + (ngrp * 8 + nn) * 64 + 2 * kq), wl2[kq]);
        }
#pragma unroll
        for (int nn = 0; nn < 8; nn++) {
            float2 f = upk2(acc[nn]);
            float r = fmaxf(f.x + f.y, 0.f);
            int node = n0 + ngrp * 8 + nn;
            g_chA[(((size_t)(2 * g)     * Bz + b) * Nn + node) * Ee + col] = r;
            g_chA[(((size_t)(2 * g + 1) * Bz + b) * Nn + node) * Ee + col] = r;
        }
    }
}

// ---------------- GRU input projection -----------------------------------
__global__ void k_xp(const float* __restrict__ S1, const float* __restrict__ S2,
                     const float* __restrict__ K1, const float* __restrict__ K2,
                     const float* __restrict__ B1, const float* __restrict__ B2)
{
    int g = blockIdx.z, b = blockIdx.y, n0 = blockIdx.x * 64;
    const float* S  = (g ? S2 : S1) + ((size_t)b * Nn + n0) * SEMD;
    const float* Wk = g ? K2 : K1;
    const float* bb = g ? B2 : B1;
    __shared__ __align__(16) float ss[64 * 64];
    int tid = threadIdx.x;                       // 192
    for (int idx = tid; idx < 64 * 64; idx += 192) ss[idx] = S[idx];
    int col = tid;
    ull wk2[32];
#pragma unroll
    for (int i = 0; i < 32; i++)
        wk2[i] = pk2(__ldg(&Wk[(2 * i) * G3H + col]), __ldg(&Wk[(2 * i + 1) * G3H + col]));
    float b0 = bb[col];
    __syncthreads();
    float* xp = g_xp + (((size_t)g * Bz + b) * Nn + n0) * G3H;
    for (int ngrp = 0; ngrp < 8; ngrp++) {
        ull acc[8];
#pragma unroll
        for (int nn = 0; nn < 8; nn++) acc[nn] = pk2(0.f, 0.f);
#pragma unroll
        for (int kq = 0; kq < 32; kq++) {
#pragma unroll
            for (int nn = 0; nn < 8; nn++)
                ffma2(acc[nn], *(const ull*)(ss + (ngrp * 8 + nn) * 64 + 2 * kq), wk2[kq]);
        }
#pragma unroll
        for (int nn = 0; nn < 8; nn++) {
            float2 f = upk2(acc[nn]);
            xp[(size_t)(ngrp * 8 + nn) * G3H + col] = f.x + f.y + b0;
        }
    }
}

// ---------------- GRU scan ------------------------------------------------
__global__ void __launch_bounds__(192, 1)
k_gru(const float* __restrict__ rk1, const float* __restrict__ rk2,
      const float* __restrict__ gb1, const float* __restrict__ gb2)
{
    int g = blockIdx.x >> 5;
    int b = blockIdx.x & 31;
    const float* rk = g ? rk2 : rk1;
    const float* gb = g ? gb2 : gb1;
    __shared__ __align__(16) float sm[12288];
    int tid = threadIdx.x;                       // 192
    for (int idx = tid; idx < 64 * G3H; idx += 192) sm[idx] = rk[idx];
    __syncthreads();
    ull rk2p[32];
#pragma unroll
    for (int i = 0; i < 32; i++)
        rk2p[i] = pk2(sm[(2 * i) * G3H + tid], sm[(2 * i + 1) * G3H + tid]);
    __syncthreads();
    float* h_sh   = sm;          // [64]
    float* pre_sh = sm + 64;     // [128]
    float* rh_sh  = sm + 192;    // [64]
    float* xh_sh  = sm + 256;    // [64]
    if (tid < 64) h_sh[tid] = 0.f;
    float bb = gb[G3H + tid];
    const float* xp = g_xp + ((size_t)g * Bz + b) * Nn * G3H;
    float* outF = g_chA + (((size_t)(2 * g)     * Bz + b) * Nn) * Ee;
    float* outR = g_chA + (((size_t)(2 * g + 1) * Bz + b) * Nn) * Ee;
    __syncthreads();
    float xnext = xp[tid];
    for (int t = 0; t < Nn; t++) {
        float xv = xnext;
        if (t + 1 < Nn) xnext = xp[(size_t)(t + 1) * G3H + tid];
        ull a0 = pk2(0.f, 0.f), a1 = a0, a2 = a0, a3 = a0;
#pragma unroll
        for (int q = 0; q < 32; q += 4) {
            ffma2(a0, *(const ull*)(h_sh + 2 * q),     rk2p[q]);
            ffma2(a1, *(const ull*)(h_sh + 2 * q + 2), rk2p[q + 1]);
            ffma2(a2, *(const ull*)(h_sh + 2 * q + 4), rk2p[q + 2]);
            ffma2(a3, *(const ull*)(h_sh + 2 * q + 6), rk2p[q + 3]);
        }
        float2 f0 = upk2(a0), f1 = upk2(a1), f2 = upk2(a2), f3 = upk2(a3);
        float pre = ((f0.x + f0.y) + (f1.x + f1.y)) + ((f2.x + f2.y) + (f3.x + f3.y)) + bb;
        if (tid < 128) pre_sh[tid] = xv + pre;
        else { rh_sh[tid - 128] = pre; xh_sh[tid - 128] = xv; }
        __syncthreads();
        if (tid < 64) {
            float z = 1.f / (1.f + __expf(-pre_sh[tid]));
            float r = 1.f / (1.f + __expf(-pre_sh[64 + tid]));
            float ag = xh_sh[tid] + r * rh_sh[tid];
            ag = fminf(fmaxf(ag, -12.f), 12.f);
            float e2 = __expf(-2.f * ag);
            float hh = (1.f - e2) / (1.f + e2);
            float hn = z * h_sh[tid] + (1.f - z) * hh;
            h_sh[tid] = hn;
            float rl = fmaxf(hn, 0.f);
            outF[(size_t)t * Ee + 64 + tid] = rl;
            outR[(size_t)t * Ee + 64 + tid] = rl;
        }
        __syncthreads();
    }
}

// ---------------- per-step transform: ghw = wh @ W_g (fp16 out) ----------
// 128 threads, 64 nodes/block, 8x8 register tile, FFMA2 over k-pairs.
#define WGT_LD 134
#define TRANS_SMEM ((128*WGT_LD + 64*128) * 4)
__global__ void __launch_bounds__(128)
k_transform(int srcA, const float* __restrict__ Wg,
            const float* __restrict__ a1w, const float* __restrict__ a1b,
            const float* __restrict__ a2w, const float* __restrict__ a2b)
{
    const float* wh = srcA ? g_chA : g_chB;
    extern __shared__ __align__(16) float dynsm[];
    float* WgT   = dynsm;                  // [128][WGT_LD] (c-major, transposed)
    float* wh_sh = dynsm + 128 * WGT_LD;   // [64][128]
    __shared__ float av[256];
    int c = blockIdx.z, b = blockIdx.y, n0 = blockIdx.x * 64;
    size_t base = (((size_t)c * Bz + b) * Nn + n0) * Ee;
    int tid = threadIdx.x;
    if (tid < 128) { av[tid] = a1w[tid]; av[128 + tid] = a2w[tid]; }
    // stage wh (float4) and WgT (transposed)
    {
        const float4* src = (const float4*)(wh + base);
        float4* dst = (float4*)wh_sh;
        for (int idx = tid; idx < 64 * 32; idx += 128) dst[idx] = src[idx];
        for (int idx = tid; idx < 128 * 128; idx += 128) {
            int k = idx >> 7, cc = idx & 127;
            WgT[cc * WGT_LD + k] = Wg[idx];
        }
    }
    __syncthreads();

    int nr = tid >> 4;        // 0..7 -> node group base nr*8
    int nc = tid & 15;        // cols: i*16+nc, i=0..7
    int nbase = nr * 8;
    ull acc[8][8];
#pragma unroll
    for (int ii = 0; ii < 8; ii++)
#pragma unroll
        for (int i = 0; i < 8; i++) acc[ii][i] = pk2(0.f, 0.f);

    for (int k0 = 0; k0 < 128; k0 += 4) {
        ull aN[8][2];
#pragma unroll
        for (int ii = 0; ii < 8; ii++) {
            const ull* p = (const ull*)(wh_sh + (nbase + ii) * 128 + k0);
            aN[ii][0] = p[0]; aN[ii][1] = p[1];
        }
#pragma unroll
        for (int i = 0; i < 8; i++) {
            const ull* q = (const ull*)(WgT + (i * 16 + nc) * WGT_LD + k0);
            ull w0 = q[0], w1 = q[1];
#pragma unroll
            for (int ii = 0; ii < 8; ii++) {
                ffma2(acc[ii][i], aN[ii][0], w0);
                ffma2(acc[ii][i], aN[ii][1], w1);
            }
        }
    }
#pragma unroll
    for (int ii = 0; ii < 8; ii++)
#pragma unroll
        for (int i = 0; i < 8; i++) {
            float2 f = upk2(acc[ii][i]);
            g_ghwh[base + (size_t)(nbase + ii) * Ee + (i * 16 + nc)] = __float2half(f.x + f.y);
        }

    // attention projections for this block's 64 nodes (4 warps x 16 nodes)
    int w = tid >> 5, lane = tid & 31;
#pragma unroll 4
    for (int ii = 0; ii < 16; ii++) {
        int node = w * 16 + ii;
        float x0 = wh_sh[node * 128 + lane];
        float x1 = wh_sh[node * 128 + 64 + lane];
        float s1 = x0 * av[lane]       + x1 * av[64 + lane];
        float s2 = x0 * av[128 + lane] + x1 * av[192 + lane];
#pragma unroll
        for (int off = 16; off; off >>= 1) {
            s1 += __shfl_xor_sync(0xffffffffu, s1, off);
            s2 += __shfl_xor_sync(0xffffffffu, s2, off);
        }
        if (lane == 0) {
            size_t idx = ((size_t)c * Bz + b) * Nn + n0 + node;
            g_ah1[idx] = s1 + a1b[0];
            g_ah2[idx] = s2 + a2b[0];
        }
    }
}

// ---------------- per-step attend: ghw staged in smem (fp16) -------------
// One block per (c,b): 512 threads = 16 warps x 32 nodes, warp-autonomous.
#define ATT_SMEM (512*128*2 + 16*128*4 + 16*128*2)
__global__ void __launch_bounds__(512)
k_attend(int srcA)
{
    const float* whc = srcA ? g_chA : g_chB;
    float*       whn = srcA ? g_chB : g_chA;
    int c = blockIdx.y, b = blockIdx.x;
    size_t cb = ((size_t)c * Bz + b) * Nn;
    extern __shared__ __align__(16) char dyn[];
    __half* ghw_sh = (__half*)dyn;                       // 512*128 halfs
    float*  p_all  = (float*)(dyn + 512 * 128 * 2);      // 16*128
    short*  nj_all = (short*)(dyn + 512 * 128 * 2 + 16 * 128 * 4);
    int tid = threadIdx.x, lane = tid & 31, w = tid >> 5;

    // stage ghw slab (128KB) into shared
    {
        const uint4* src = (const uint4*)(g_ghwh + cb * Ee);
        uint4* dst = (uint4*)ghw_sh;
        for (int idx = tid; idx < 512 * 128 * 2 / 16; idx += 512) dst[idx] = src[idx];
    }
    __syncthreads();

    float* p_w  = p_all  + w * MAXD;
    short* nj_w = nj_all + w * MAXD;
    const uint2* gptr = (const uint2*)ghw_sh;

    for (int ii = 0; ii < 32; ii++) {
        int i = w * 32 + ii;
        int cnt = g_cnt[cb + i];
        float ah1i = g_ah1[cb + i];
        const short* adjr = g_adj + (cb + i) * MAXD;
        float e[4]; short njr[4];
#pragma unroll
        for (int q = 0; q < 4; q++) {
            int idx = lane + 32 * q;
            if (idx < cnt) {
                njr[q] = adjr[idx];
                float x = ah1i + g_ah2[cb + njr[q]];
                e[q] = x > 0.f ? x : 0.2f * x;
            } else { e[q] = -3.0e38f; njr[q] = 0; }
        }
        float m = fmaxf(fmaxf(e[0], e[1]), fmaxf(e[2], e[3]));
#pragma unroll
        for (int off = 16; off; off >>= 1)
            m = fmaxf(m, __shfl_xor_sync(0xffffffffu, m, off));
        float p[4]; float s = 0.f;
#pragma unroll
        for (int q = 0; q < 4; q++) {
            p[q] = (lane + 32 * q < cnt) ? __expf(e[q] - m) : 0.f;
            s += p[q];
        }
#pragma unroll
        for (int off = 16; off; off >>= 1)
            s += __shfl_xor_sync(0xffffffffu, s, off);
        float inv = cnt > 0 ? 1.f / s : 0.f;
#pragma unroll
        for (int q = 0; q < 4; q++) {
            p_w[lane + 32 * q]  = p[q] * inv;
            nj_w[lane + 32 * q] = njr[q];
        }
        __syncwarp();
        float4 acc = make_float4(0.f, 0.f, 0.f, 0.f);
#pragma unroll 2
        for (int j = 0; j < cnt; j++) {
            int nj = nj_w[j];
            float pj = p_w[j];
            uint2 hv = gptr[nj * 32 + lane];
            float2 f01 = __half22float2(*reinterpret_cast<__half2*>(&hv.x));
            float2 f23 = __half22float2(*reinterpret_cast<__half2*>(&hv.y));
            acc.x = fmaf(pj, f01.x, acc.x);
            acc.y = fmaf(pj, f01.y, acc.y);
            acc.z = fmaf(pj, f23.x, acc.z);
            acc.w = fmaf(pj, f23.y, acc.w);
        }
        float4 wc = *(const float4*)(whc + (cb + i) * Ee + 4 * lane);
        float4 v;
        v.x = wc.x + acc.x; v.y = wc.y + acc.y;
        v.z = wc.z + acc.z; v.w = wc.w + acc.w;
        v.x = v.x > 0.f ? v.x : expm1f(v.x);
        v.y = v.y > 0.f ? v.y : expm1f(v.y);
        v.z = v.z > 0.f ? v.z : expm1f(v.z);
        v.w = v.w > 0.f ? v.w : expm1f(v.w);
        *(float4*)(whn + (cb + i) * Ee + 4 * lane) = v;
        __syncwarp();
    }
}

// ---------------- sum over nodes + output projection ---------------------
__global__ void k_reduce(const float* __restrict__ Wout,
                         const float* __restrict__ bout)
{
    int b = blockIdx.x, g = blockIdx.y;
    int tid = threadIdx.x;                       // 128
    __shared__ float mid[128];
    const float* f = g_chB + ((size_t)(2 * g)     * Bz + b) * Nn * Ee;
    const float* r = g_chB + ((size_t)(2 * g + 1) * Bz + b) * Nn * Ee;
    float s = 0.f;
#pragma unroll 4
    for (int n = 0; n < Nn; n++)
        s += f[(size_t)n * Ee + tid] + r[(size_t)n * Ee + tid];
    mid[tid] = s;
    __syncthreads();
    if (tid < OUTD) {
        float acc = bout[tid];
#pragma unroll 8
        for (int e = 0; e < Ee; e++)
            acc = fmaf(mid[e], __ldg(&Wout[e * OUTD + tid]), acc);
        g_emb[((size_t)g * Bz + b) * OUTD + tid] = acc;
    }
}

// ---------------- cosine similarity -> (1+cos)/2 -------------------------
__global__ void k_cos(float* __restrict__ out)
{
    int b = blockIdx.x;
    int tid = threadIdx.x, lane = tid & 31, w = tid >> 5;   // 64 threads
    float x1 = g_emb[(size_t)b * OUTD + tid];
    float x2 = g_emb[(size_t)(Bz + b) * OUTD + tid];
    float d = x1 * x2, n1 = x1 * x1, n2 = x2 * x2;
#pragma unroll
    for (int off = 16; off; off >>= 1) {
        d  += __shfl_xor_sync(0xffffffffu, d,  off);
        n1 += __shfl_xor_sync(0xffffffffu, n1, off);
        n2 += __shfl_xor_sync(0xffffffffu, n2, off);
    }
    __shared__ float sh[6];
    if (lane == 0) { sh[w * 3] = d; sh[w * 3 + 1] = n1; sh[w * 3 + 2] = n2; }
    __syncthreads();
    if (tid == 0) {
        float dd = sh[0] + sh[3], a = sh[1] + sh[4], c2 = sh[2] + sh[5];
        float denom = fmaxf(sqrtf(a), 1e-12f) * fmaxf(sqrtf(c2), 1e-12f);
        out[b] = 0.5f * (1.f + dd / denom);
    }
}

// ---------------- launch sequence ----------------------------------------
extern "C" void kernel_launch(void* const* d_in, const int* in_sizes, int n_in,
                              void* d_out, int out_size)
{
    const float* CFG1 = (const float*)d_in[0];
    const float* LIT1 = (const float*)d_in[2];
    const float* SEM1 = (const float*)d_in[3];
    const float* CFG2 = (const float*)d_in[4];
    const float* LIT2 = (const float*)d_in[6];
    const float* SEM2 = (const float*)d_in[7];
    const float* Wl1  = (const float*)d_in[8];
    const float* gk1  = (const float*)d_in[9];
    const float* grk1 = (const float*)d_in[10];
    const float* gb1  = (const float*)d_in[11];
    const float* Wl2  = (const float*)d_in[12];
    const float* gk2  = (const float*)d_in[13];
    const float* grk2 = (const float*)d_in[14];
    const float* gb2  = (const float*)d_in[15];
    const float* a1w  = (const float*)d_in[16];
    const float* a1b  = (const float*)d_in[17];
    const float* a2w  = (const float*)d_in[18];
    const float* a2b  = (const float*)d_in[19];
    const float* Wg   = (const float*)d_in[20];
    const float* Wout = (const float*)d_in[21];
    const float* bout = (const float*)d_in[22];

    cudaFuncSetAttribute(k_transform, cudaFuncAttributeMaxDynamicSharedMemorySize, TRANS_SMEM);
    cudaFuncSetAttribute(k_attend,    cudaFuncAttributeMaxDynamicSharedMemorySize, ATT_SMEM);

    k_build_fwd<<<dim3(64, 32, 2), 256>>>(CFG1, CFG2);
    k_build_rev<<<dim3(2, 32, 2), 256>>>(CFG1, CFG2);
    k_lit<<<dim3(8, 32, 2), 256>>>(LIT1, LIT2, Wl1, Wl2);
    k_xp <<<dim3(8, 32, 2), 192>>>(SEM1, SEM2, gk1, gk2, gb1, gb2);
    k_gru<<<64, 192>>>(grk1, grk2, gb1, gb2);

    int srcA = 1;
    for (int s = 0; s < 3; s++) {
        k_transform<<<dim3(8, 32, 4), 128, TRANS_SMEM>>>(srcA, Wg, a1w, a1b, a2w, a2b);
        k_attend   <<<dim3(32, 4), 512, ATT_SMEM>>>(srcA);
        srcA ^= 1;
    }
    // after 3 steps, final states are in g_chB
    k_reduce<<<dim3(32, 2), 128>>>(Wout, bout);
    k_cos<<<32, 64>>>((float*)d_out);
}

// round 15
// speedup vs baseline: 1.5279x; 1.1690x over previous
#include <cuda_runtime.h>
#include <cuda_fp16.h>
#include <math.h>

#define Bz   32
#define Nn   512
#define LITD 64
#define SEMD 64
#define Hh   64
#define Ee   128
#define G3H  192
#define OUTD 64
#define MAXD 128

typedef unsigned long long ull;

// ---------------- packed fp32x2 helpers ----------------------------------
__device__ __forceinline__ ull pk2(float x, float y) {
    union { float2 f; ull u; } t; t.f = make_float2(x, y); return t.u;
}
__device__ __forceinline__ float2 upk2(ull u) {
    union { float2 f; ull u; } t; t.u = u; return t.f;
}
__device__ __forceinline__ void ffma2(ull& d, ull a, ull b) {
    asm("fma.rn.f32x2 %0, %1, %2, %0;" : "+l"(d) : "l"(a), "l"(b));
}

// ---------------- device scratch (static, no allocations) ----------------
__device__ float  g_xp [2u*Bz*Nn*G3H];
__device__ float  g_chA[4u*Bz*Nn*Ee];
__device__ float  g_chB[4u*Bz*Nn*Ee];
__device__ __half g_ghwh[4u*Bz*Nn*Ee];
__device__ float  g_ah1[4u*Bz*Nn];
__device__ float  g_ah2[4u*Bz*Nn];
__device__ short  g_adj[4u*Bz*Nn*MAXD];
__device__ int    g_cnt[4u*Bz*Nn];
__device__ float  g_emb[2u*Bz*OUTD];

// ---------------- adjacency builders -------------------------------------
__global__ void k_build_fwd(const float* __restrict__ A1,
                            const float* __restrict__ A2)
{
    int g = blockIdx.z;
    const float* A = g ? A2 : A1;
    int b = blockIdx.y;
    int w = threadIdx.x >> 5, lane = threadIdx.x & 31;
    int row = blockIdx.x * 8 + w;
    int v = g * 2;
    const float* Ar = A + ((size_t)b * Nn + row) * Nn;
    short* out = g_adj + (((size_t)v * Bz + b) * Nn + row) * MAXD;
    int cnt = 0;
    for (int j0 = 0; j0 < Nn; j0 += 32) {
        float val = Ar[j0 + lane];
        unsigned m = __ballot_sync(0xffffffffu, val > 0.5f);
        if (val > 0.5f) {
            int pos = cnt + __popc(m & ((1u << lane) - 1u));
            if (pos < MAXD) out[pos] = (short)(j0 + lane);
        }
        cnt += __popc(m);
    }
    if (lane == 0) g_cnt[((size_t)v * Bz + b) * Nn + row] = cnt < MAXD ? cnt : MAXD;
}

__global__ void k_build_rev(const float* __restrict__ A1,
                            const float* __restrict__ A2)
{
    int g = blockIdx.z;
    const float* A = g ? A2 : A1;
    int b = blockIdx.y;
    int w = threadIdx.x >> 5, lane = threadIdx.x & 31;
    int j = (blockIdx.x * 8 + w) * 32 + lane;
    int v = g * 2 + 1;
    const float* Ab = A + (size_t)b * Nn * Nn;
    short* out = g_adj + (((size_t)v * Bz + b) * Nn + j) * MAXD;
    int cnt = 0;
    for (int i = 0; i < Nn; i += 4) {
        float v0 = Ab[(size_t)(i + 0) * Nn + j];
        float v1 = Ab[(size_t)(i + 1) * Nn + j];
        float v2 = Ab[(size_t)(i + 2) * Nn + j];
        float v3 = Ab[(size_t)(i + 3) * Nn + j];
        if (v0 > 0.5f && cnt < MAXD) out[cnt++] = (short)(i + 0);
        if (v1 > 0.5f && cnt < MAXD) out[cnt++] = (short)(i + 1);
        if (v2 > 0.5f && cnt < MAXD) out[cnt++] = (short)(i + 2);
        if (v3 > 0.5f && cnt < MAXD) out[cnt++] = (short)(i + 3);
    }
    g_cnt[((size_t)v * Bz + b) * Nn + j] = cnt;
}

// ---------------- literal path: relu(lit @ Wl), 32 nodes/block -----------
__global__ void __launch_bounds__(256)
k_lit(const float* __restrict__ L1, const float* __restrict__ L2,
      const float* __restrict__ Wl1, const float* __restrict__ Wl2)
{
    int g = blockIdx.z, b = blockIdx.y, n0 = blockIdx.x * 32;
    const float* L  = (g ? L2 : L1) + ((size_t)b * Nn + n0) * LITD;
    const float* Wl = g ? Wl2 : Wl1;
    __shared__ __align__(16) float ls[32 * 64];
    int tid = threadIdx.x;                       // 256
    for (int idx = tid; idx < 32 * 64; idx += 256) ls[idx] = L[idx];
    int col = tid & 63, q = tid >> 6;            // q = node group 0..3
    ull wl2[32];
#pragma unroll
    for (int i = 0; i < 32; i++)
        wl2[i] = pk2(__ldg(&Wl[(2 * i) * 64 + col]), __ldg(&Wl[(2 * i + 1) * 64 + col]));
    __syncthreads();
    {
        ull acc[8];
#pragma unroll
        for (int nn = 0; nn < 8; nn++) acc[nn] = pk2(0.f, 0.f);
#pragma unroll
        for (int kq = 0; kq < 32; kq++) {
#pragma unroll
            for (int nn = 0; nn < 8; nn++)
                ffma2(acc[nn], *(const ull*)(ls + (q * 8 + nn) * 64 + 2 * kq), wl2[kq]);
        }
#pragma unroll
        for (int nn = 0; nn < 8; nn++) {
            float2 f = upk2(acc[nn]);
            float r = fmaxf(f.x + f.y, 0.f);
            int node = n0 + q * 8 + nn;
            g_chA[(((size_t)(2 * g)     * Bz + b) * Nn + node) * Ee + col] = r;
            g_chA[(((size_t)(2 * g + 1) * Bz + b) * Nn + node) * Ee + col] = r;
        }
    }
}

// ---------------- GRU input projection, 32 nodes/block -------------------
__global__ void __launch_bounds__(192)
k_xp(const float* __restrict__ S1, const float* __restrict__ S2,
     const float* __restrict__ K1, const float* __restrict__ K2,
     const float* __restrict__ B1, const float* __restrict__ B2)
{
    int g = blockIdx.z, b = blockIdx.y, n0 = blockIdx.x * 32;
    const float* S  = (g ? S2 : S1) + ((size_t)b * Nn + n0) * SEMD;
    const float* Wk = g ? K2 : K1;
    const float* bb = g ? B2 : B1;
    __shared__ __align__(16) float ss[32 * 64];
    int tid = threadIdx.x;                       // 192
    for (int idx = tid; idx < 32 * 64; idx += 192) ss[idx] = S[idx];
    int col = tid;
    ull wk2[32];
#pragma unroll
    for (int i = 0; i < 32; i++)
        wk2[i] = pk2(__ldg(&Wk[(2 * i) * G3H + col]), __ldg(&Wk[(2 * i + 1) * G3H + col]));
    float b0 = bb[col];
    __syncthreads();
    float* xp = g_xp + (((size_t)g * Bz + b) * Nn + n0) * G3H;
    for (int ngrp = 0; ngrp < 4; ngrp++) {
        ull acc[8];
#pragma unroll
        for (int nn = 0; nn < 8; nn++) acc[nn] = pk2(0.f, 0.f);
#pragma unroll
        for (int kq = 0; kq < 32; kq++) {
#pragma unroll
            for (int nn = 0; nn < 8; nn++)
                ffma2(acc[nn], *(const ull*)(ss + (ngrp * 8 + nn) * 64 + 2 * kq), wk2[kq]);
        }
#pragma unroll
        for (int nn = 0; nn < 8; nn++) {
            float2 f = upk2(acc[nn]);
            xp[(size_t)(ngrp * 8 + nn) * G3H + col] = f.x + f.y + b0;
        }
    }
}

// ---------------- GRU scan ------------------------------------------------
__global__ void __launch_bounds__(192, 1)
k_gru(const float* __restrict__ rk1, const float* __restrict__ rk2,
      const float* __restrict__ gb1, const float* __restrict__ gb2)
{
    int g = blockIdx.x >> 5;
    int b = blockIdx.x & 31;
    const float* rk = g ? rk2 : rk1;
    const float* gb = g ? gb2 : gb1;
    __shared__ __align__(16) float sm[12288];
    int tid = threadIdx.x;                       // 192
    for (int idx = tid; idx < 64 * G3H; idx += 192) sm[idx] = rk[idx];
    __syncthreads();
    ull rk2p[32];
#pragma unroll
    for (int i = 0; i < 32; i++)
        rk2p[i] = pk2(sm[(2 * i) * G3H + tid], sm[(2 * i + 1) * G3H + tid]);
    __syncthreads();
    float* h_sh   = sm;          // [64]
    float* pre_sh = sm + 64;     // [128]
    float* rh_sh  = sm + 192;    // [64]
    float* xh_sh  = sm + 256;    // [64]
    if (tid < 64) h_sh[tid] = 0.f;
    float bb = gb[G3H + tid];
    const float* xp = g_xp + ((size_t)g * Bz + b) * Nn * G3H;
    float* outF = g_chA + (((size_t)(2 * g)     * Bz + b) * Nn) * Ee;
    float* outR = g_chA + (((size_t)(2 * g + 1) * Bz + b) * Nn) * Ee;
    __syncthreads();
    float xnext = xp[tid];
    for (int t = 0; t < Nn; t++) {
        float xv = xnext;
        if (t + 1 < Nn) xnext = xp[(size_t)(t + 1) * G3H + tid];
        ull a0 = pk2(0.f, 0.f), a1 = a0, a2 = a0, a3 = a0;
#pragma unroll
        for (int q = 0; q < 32; q += 4) {
            ffma2(a0, *(const ull*)(h_sh + 2 * q),     rk2p[q]);
            ffma2(a1, *(const ull*)(h_sh + 2 * q + 2), rk2p[q + 1]);
            ffma2(a2, *(const ull*)(h_sh + 2 * q + 4), rk2p[q + 2]);
            ffma2(a3, *(const ull*)(h_sh + 2 * q + 6), rk2p[q + 3]);
        }
        float2 f0 = upk2(a0), f1 = upk2(a1), f2 = upk2(a2), f3 = upk2(a3);
        float pre = ((f0.x + f0.y) + (f1.x + f1.y)) + ((f2.x + f2.y) + (f3.x + f3.y)) + bb;
        if (tid < 128) pre_sh[tid] = xv + pre;
        else { rh_sh[tid - 128] = pre; xh_sh[tid - 128] = xv; }
        __syncthreads();
        if (tid < 64) {
            float z = 1.f / (1.f + __expf(-pre_sh[tid]));
            float r = 1.f / (1.f + __expf(-pre_sh[64 + tid]));
            float ag = xh_sh[tid] + r * rh_sh[tid];
            ag = fminf(fmaxf(ag, -12.f), 12.f);
            float e2 = __expf(-2.f * ag);
            float hh = (1.f - e2) / (1.f + e2);
            float hn = z * h_sh[tid] + (1.f - z) * hh;
            h_sh[tid] = hn;
            float rl = fmaxf(hn, 0.f);
            outF[(size_t)t * Ee + 64 + tid] = rl;
            outR[(size_t)t * Ee + 64 + tid] = rl;
        }
        __syncthreads();
    }
}

// ---------------- per-step transform: ghw = wh @ W_g (fp16 out) ----------
// 256 threads, 64 nodes/block, per-thread tile 8 nodes x 4 cols (32 accs).
#define WGT_LD 130
#define TRANS_SMEM ((128*WGT_LD + 64*128) * 4)
__global__ void __launch_bounds__(256)
k_transform(int srcA, const float* __restrict__ Wg,
            const float* __restrict__ a1w, const float* __restrict__ a1b,
            const float* __restrict__ a2w, const float* __restrict__ a2b)
{
    const float* wh = srcA ? g_chA : g_chB;
    extern __shared__ __align__(16) float dynsm[];
    float* WgT   = dynsm;                  // [128 cols][WGT_LD k]
    float* wh_sh = dynsm + 128 * WGT_LD;   // [64 nodes][128 k]
    __shared__ float av[256];
    int c = blockIdx.z, b = blockIdx.y, n0 = blockIdx.x * 64;
    size_t base = (((size_t)c * Bz + b) * Nn + n0) * Ee;
    int tid = threadIdx.x;
    if (tid < 128) av[tid] = a1w[tid];
    else           av[tid] = a2w[tid - 128];
    {
        const float4* src = (const float4*)(wh + base);
        float4* dst = (float4*)wh_sh;
        for (int idx = tid; idx < 64 * 32; idx += 256) dst[idx] = src[idx];
        for (int idx = tid; idx < 128 * 128; idx += 256) {
            int k = idx >> 7, cc = idx & 127;
            WgT[cc * WGT_LD + k] = Wg[idx];
        }
    }
    __syncthreads();

    int ng = tid >> 5;         // node group 0..7 (nodes ng*8 .. +7)
    int cl = tid & 31;         // col thread: cols i*32+cl, i=0..3
    ull acc[8][4];
#pragma unroll
    for (int ii = 0; ii < 8; ii++)
#pragma unroll
        for (int i = 0; i < 4; i++) acc[ii][i] = pk2(0.f, 0.f);

#pragma unroll 4
    for (int k0 = 0; k0 < 128; k0 += 2) {
        ull aN[8];
#pragma unroll
        for (int ii = 0; ii < 8; ii++)
            aN[ii] = *(const ull*)(wh_sh + (ng * 8 + ii) * 128 + k0);
        ull wv[4];
#pragma unroll
        for (int i = 0; i < 4; i++)
            wv[i] = *(const ull*)(WgT + (i * 32 + cl) * WGT_LD + k0);
#pragma unroll
        for (int ii = 0; ii < 8; ii++)
#pragma unroll
            for (int i = 0; i < 4; i++)
                ffma2(acc[ii][i], aN[ii], wv[i]);
    }
#pragma unroll
    for (int ii = 0; ii < 8; ii++)
#pragma unroll
        for (int i = 0; i < 4; i++) {
            float2 f = upk2(acc[ii][i]);
            g_ghwh[base + (size_t)(ng * 8 + ii) * Ee + (i * 32 + cl)] =
                __float2half(f.x + f.y);
        }

    // attention projections: 8 warps x 8 nodes
    int w = tid >> 5, lane = tid & 31;
#pragma unroll
    for (int ii = 0; ii < 8; ii++) {
        int node = w * 8 + ii;
        float x0 = wh_sh[node * 128 + lane];
        float x1 = wh_sh[node * 128 + 64 + lane];
        float s1 = x0 * av[lane]       + x1 * av[64 + lane];
        float s2 = x0 * av[128 + lane] + x1 * av[192 + lane];
#pragma unroll
        for (int off = 16; off; off >>= 1) {
            s1 += __shfl_xor_sync(0xffffffffu, s1, off);
            s2 += __shfl_xor_sync(0xffffffffu, s2, off);
        }
        if (lane == 0) {
            size_t idx = ((size_t)c * Bz + b) * Nn + n0 + node;
            g_ah1[idx] = s1 + a1b[0];
            g_ah2[idx] = s2 + a2b[0];
        }
    }
}

// ---------------- per-step attend: ghw staged in smem (fp16) -------------
// One block per (c,b): 1024 threads = 32 warps x 16 nodes.
#define ATT_SMEM (512*128*2 + 32*128*4 + 32*128*2)
__global__ void __launch_bounds__(1024)
k_attend(int srcA)
{
    const float* whc = srcA ? g_chA : g_chB;
    float*       whn = srcA ? g_chB : g_chA;
    int c = blockIdx.y, b = blockIdx.x;
    size_t cb = ((size_t)c * Bz + b) * Nn;
    extern __shared__ __align__(16) char dyn[];
    __half* ghw_sh = (__half*)dyn;                       // 512*128 halfs
    float*  p_all  = (float*)(dyn + 512 * 128 * 2);      // 32*128
    short*  nj_all = (short*)(dyn + 512 * 128 * 2 + 32 * 128 * 4);
    int tid = threadIdx.x, lane = tid & 31, w = tid >> 5;

    {
        const uint4* src = (const uint4*)(g_ghwh + cb * Ee);
        uint4* dst = (uint4*)ghw_sh;
        for (int idx = tid; idx < 512 * 128 * 2 / 16; idx += 1024) dst[idx] = src[idx];
    }
    __syncthreads();

    float* p_w  = p_all  + w * MAXD;
    short* nj_w = nj_all + w * MAXD;
    const uint2* gptr = (const uint2*)ghw_sh;

    for (int ii = 0; ii < 16; ii++) {
        int i = w * 16 + ii;
        int cnt = g_cnt[cb + i];
        float ah1i = g_ah1[cb + i];
        const short* adjr = g_adj + (cb + i) * MAXD;
        float e[4]; short njr[4];
#pragma unroll
        for (int q = 0; q < 4; q++) {
            int idx = lane + 32 * q;
            if (idx < cnt) {
                njr[q] = adjr[idx];
                float x = ah1i + g_ah2[cb + njr[q]];
                e[q] = x > 0.f ? x : 0.2f * x;
            } else { e[q] = -3.0e38f; njr[q] = 0; }
        }
        float m = fmaxf(fmaxf(e[0], e[1]), fmaxf(e[2], e[3]));
#pragma unroll
        for (int off = 16; off; off >>= 1)
            m = fmaxf(m, __shfl_xor_sync(0xffffffffu, m, off));
        float p[4]; float s = 0.f;
#pragma unroll
        for (int q = 0; q < 4; q++) {
            p[q] = (lane + 32 * q < cnt) ? __expf(e[q] - m) : 0.f;
            s += p[q];
        }
#pragma unroll
        for (int off = 16; off; off >>= 1)
            s += __shfl_xor_sync(0xffffffffu, s, off);
        float inv = cnt > 0 ? 1.f / s : 0.f;
#pragma unroll
        for (int q = 0; q < 4; q++) {
            p_w[lane + 32 * q]  = p[q] * inv;
            nj_w[lane + 32 * q] = njr[q];
        }
        __syncwarp();
        float4 acc = make_float4(0.f, 0.f, 0.f, 0.f);
#pragma unroll 2
        for (int j = 0; j < cnt; j++) {
            int nj = nj_w[j];
            float pj = p_w[j];
            uint2 hv = gptr[nj * 32 + lane];
            float2 f01 = __half22float2(*reinterpret_cast<__half2*>(&hv.x));
            float2 f23 = __half22float2(*reinterpret_cast<__half2*>(&hv.y));
            acc.x = fmaf(pj, f01.x, acc.x);
            acc.y = fmaf(pj, f01.y, acc.y);
            acc.z = fmaf(pj, f23.x, acc.z);
            acc.w = fmaf(pj, f23.y, acc.w);
        }
        float4 wc = *(const float4*)(whc + (cb + i) * Ee + 4 * lane);
        float4 v;
        v.x = wc.x + acc.x; v.y = wc.y + acc.y;
        v.z = wc.z + acc.z; v.w = wc.w + acc.w;
        v.x = v.x > 0.f ? v.x : expm1f(v.x);
        v.y = v.y > 0.f ? v.y : expm1f(v.y);
        v.z = v.z > 0.f ? v.z : expm1f(v.z);
        v.w = v.w > 0.f ? v.w : expm1f(v.w);
        *(float4*)(whn + (cb + i) * Ee + 4 * lane) = v;
        __syncwarp();
    }
}

// ---------------- sum over nodes + output projection ---------------------
__global__ void k_reduce(const float* __restrict__ Wout,
                         const float* __restrict__ bout)
{
    int b = blockIdx.x, g = blockIdx.y;
    int tid = threadIdx.x;                       // 128
    __shared__ float mid[128];
    const float* f = g_chB + ((size_t)(2 * g)     * Bz + b) * Nn * Ee;
    const float* r = g_chB + ((size_t)(2 * g + 1) * Bz + b) * Nn * Ee;
    float s = 0.f;
#pragma unroll 4
    for (int n = 0; n < Nn; n++)
        s += f[(size_t)n * Ee + tid] + r[(size_t)n * Ee + tid];
    mid[tid] = s;
    __syncthreads();
    if (tid < OUTD) {
        float acc = bout[tid];
#pragma unroll 8
        for (int e = 0; e < Ee; e++)
            acc = fmaf(mid[e], __ldg(&Wout[e * OUTD + tid]), acc);
        g_emb[((size_t)g * Bz + b) * OUTD + tid] = acc;
    }
}

// ---------------- cosine similarity -> (1+cos)/2 -------------------------
__global__ void k_cos(float* __restrict__ out)
{
    int b = blockIdx.x;
    int tid = threadIdx.x, lane = tid & 31, w = tid >> 5;   // 64 threads
    float x1 = g_emb[(size_t)b * OUTD + tid];
    float x2 = g_emb[(size_t)(Bz + b) * OUTD + tid];
    float d = x1 * x2, n1 = x1 * x1, n2 = x2 * x2;
#pragma unroll
    for (int off = 16; off; off >>= 1) {
        d  += __shfl_xor_sync(0xffffffffu, d,  off);
        n1 += __shfl_xor_sync(0xffffffffu, n1, off);
        n2 += __shfl_xor_sync(0xffffffffu, n2, off);
    }
    __shared__ float sh[6];
    if (lane == 0) { sh[w * 3] = d; sh[w * 3 + 1] = n1; sh[w * 3 + 2] = n2; }
    __syncthreads();
    if (tid == 0) {
        float dd = sh[0] + sh[3], a = sh[1] + sh[4], c2 = sh[2] + sh[5];
        float denom = fmaxf(sqrtf(a), 1e-12f) * fmaxf(sqrtf(c2), 1e-12f);
        out[b] = 0.5f * (1.f + dd / denom);
    }
}

// ---------------- launch sequence ----------------------------------------
extern "C" void kernel_launch(void* const* d_in, const int* in_sizes, int n_in,
                              void* d_out, int out_size)
{
    const float* CFG1 = (const float*)d_in[0];
    const float* LIT1 = (const float*)d_in[2];
    const float* SEM1 = (const float*)d_in[3];
    const float* CFG2 = (const float*)d_in[4];
    const float* LIT2 = (const float*)d_in[6];
    const float* SEM2 = (const float*)d_in[7];
    const float* Wl1  = (const float*)d_in[8];
    const float* gk1  = (const float*)d_in[9];
    const float* grk1 = (const float*)d_in[10];
    const float* gb1  = (const float*)d_in[11];
    const float* Wl2  = (const float*)d_in[12];
    const float* gk2  = (const float*)d_in[13];
    const float* grk2 = (const float*)d_in[14];
    const float* gb2  = (const float*)d_in[15];
    const float* a1w  = (const float*)d_in[16];
    const float* a1b  = (const float*)d_in[17];
    const float* a2w  = (const float*)d_in[18];
    const float* a2b  = (const float*)d_in[19];
    const float* Wg   = (const float*)d_in[20];
    const float* Wout = (const float*)d_in[21];
    const float* bout = (const float*)d_in[22];

    cudaFuncSetAttribute(k_transform, cudaFuncAttributeMaxDynamicSharedMemorySize, TRANS_SMEM);
    cudaFuncSetAttribute(k_attend,    cudaFuncAttributeMaxDynamicSharedMemorySize, ATT_SMEM);

    k_build_fwd<<<dim3(64, 32, 2), 256>>>(CFG1, CFG2);
    k_build_rev<<<dim3(2, 32, 2), 256>>>(CFG1, CFG2);
    k_lit<<<dim3(16, 32, 2), 256>>>(LIT1, LIT2, Wl1, Wl2);
    k_xp <<<dim3(16, 32, 2), 192>>>(SEM1, SEM2, gk1, gk2, gb1, gb2);
    k_gru<<<64, 192>>>(grk1, grk2, gb1, gb2);

    int srcA = 1;
    for (int s = 0; s < 3; s++) {
        k_transform<<<dim3(8, 32, 4), 256, TRANS_SMEM>>>(srcA, Wg, a1w, a1b, a2w, a2b);
        k_attend   <<<dim3(32, 4), 1024, ATT_SMEM>>>(srcA);
        srcA ^= 1;
    }
    k_reduce<<<dim3(32, 2), 128>>>(Wout, bout);
    k_cos<<<32, 64>>>((float*)d_out);
}

// round 16
// speedup vs baseline: 1.6706x; 1.0934x over previous
#include <cuda_runtime.h>
#include <cuda_fp16.h>
#include <mma.h>
#include <math.h>
using namespace nvcuda;

#define Bz   32
#define Nn   512
#define LITD 64
#define SEMD 64
#define Hh   64
#define Ee   128
#define G3H  192
#define OUTD 64
#define MAXD 128

typedef unsigned long long ull;

// ---------------- packed fp32x2 helpers ----------------------------------
__device__ __forceinline__ ull pk2(float x, float y) {
    union { float2 f; ull u; } t; t.f = make_float2(x, y); return t.u;
}
__device__ __forceinline__ float2 upk2(ull u) {
    union { float2 f; ull u; } t; t.u = u; return t.f;
}
__device__ __forceinline__ void ffma2(ull& d, ull a, ull b) {
    asm("fma.rn.f32x2 %0, %1, %2, %0;" : "+l"(d) : "l"(a), "l"(b));
}

// ---------------- device scratch (static, no allocations) ----------------
__device__ float  g_xp [2u*Bz*Nn*G3H];
__device__ float  g_chA[4u*Bz*Nn*Ee];
__device__ float  g_chB[4u*Bz*Nn*Ee];
__device__ __half g_whAh[4u*Bz*Nn*Ee];  // fp16 mirror of chA
__device__ __half g_whBh[4u*Bz*Nn*Ee];  // fp16 mirror of chB
__device__ __half g_Wgh[Ee*Ee];         // Wg in fp16
__device__ __half g_ghwh[4u*Bz*Nn*Ee];
__device__ float  g_ah1[4u*Bz*Nn];
__device__ float  g_ah2[4u*Bz*Nn];
__device__ short  g_adj[4u*Bz*Nn*MAXD];
__device__ int    g_cnt[4u*Bz*Nn];
__device__ float  g_emb[2u*Bz*OUTD];

// ---------------- Wg fp32 -> fp16 ----------------------------------------
__global__ void k_prep(const float* __restrict__ Wg)
{
    int i = blockIdx.x * 1024 + threadIdx.x;
    if (i < Ee * Ee) g_Wgh[i] = __float2half(Wg[i]);
}

// ---------------- adjacency builders -------------------------------------
__global__ void k_build_fwd(const float* __restrict__ A1,
                            const float* __restrict__ A2)
{
    int g = blockIdx.z;
    const float* A = g ? A2 : A1;
    int b = blockIdx.y;
    int w = threadIdx.x >> 5, lane = threadIdx.x & 31;
    int row = blockIdx.x * 8 + w;
    int v = g * 2;
    const float* Ar = A + ((size_t)b * Nn + row) * Nn;
    short* out = g_adj + (((size_t)v * Bz + b) * Nn + row) * MAXD;
    int cnt = 0;
    for (int j0 = 0; j0 < Nn; j0 += 32) {
        float val = Ar[j0 + lane];
        unsigned m = __ballot_sync(0xffffffffu, val > 0.5f);
        if (val > 0.5f) {
            int pos = cnt + __popc(m & ((1u << lane) - 1u));
            if (pos < MAXD) out[pos] = (short)(j0 + lane);
        }
        cnt += __popc(m);
    }
    if (lane == 0) g_cnt[((size_t)v * Bz + b) * Nn + row] = cnt < MAXD ? cnt : MAXD;
}

__global__ void k_build_rev(const float* __restrict__ A1,
                            const float* __restrict__ A2)
{
    int g = blockIdx.z;
    const float* A = g ? A2 : A1;
    int b = blockIdx.y;
    int w = threadIdx.x >> 5, lane = threadIdx.x & 31;
    int j = (blockIdx.x * 8 + w) * 32 + lane;
    int v = g * 2 + 1;
    const float* Ab = A + (size_t)b * Nn * Nn;
    short* out = g_adj + (((size_t)v * Bz + b) * Nn + j) * MAXD;
    int cnt = 0;
    for (int i = 0; i < Nn; i += 4) {
        float v0 = Ab[(size_t)(i + 0) * Nn + j];
        float v1 = Ab[(size_t)(i + 1) * Nn + j];
        float v2 = Ab[(size_t)(i + 2) * Nn + j];
        float v3 = Ab[(size_t)(i + 3) * Nn + j];
        if (v0 > 0.5f && cnt < MAXD) out[cnt++] = (short)(i + 0);
        if (v1 > 0.5f && cnt < MAXD) out[cnt++] = (short)(i + 1);
        if (v2 > 0.5f && cnt < MAXD) out[cnt++] = (short)(i + 2);
        if (v3 > 0.5f && cnt < MAXD) out[cnt++] = (short)(i + 3);
    }
    g_cnt[((size_t)v * Bz + b) * Nn + j] = cnt;
}

// ---------------- literal path: relu(lit @ Wl), 32 nodes/block -----------
__global__ void __launch_bounds__(256)
k_lit(const float* __restrict__ L1, const float* __restrict__ L2,
      const float* __restrict__ Wl1, const float* __restrict__ Wl2)
{
    int g = blockIdx.z, b = blockIdx.y, n0 = blockIdx.x * 32;
    const float* L  = (g ? L2 : L1) + ((size_t)b * Nn + n0) * LITD;
    const float* Wl = g ? Wl2 : Wl1;
    __shared__ __align__(16) float ls[32 * 64];
    int tid = threadIdx.x;                       // 256
    for (int idx = tid; idx < 32 * 64; idx += 256) ls[idx] = L[idx];
    int col = tid & 63, q = tid >> 6;            // q = node group 0..3
    ull wl2[32];
#pragma unroll
    for (int i = 0; i < 32; i++)
        wl2[i] = pk2(__ldg(&Wl[(2 * i) * 64 + col]), __ldg(&Wl[(2 * i + 1) * 64 + col]));
    __syncthreads();
    {
        ull acc[8];
#pragma unroll
        for (int nn = 0; nn < 8; nn++) acc[nn] = pk2(0.f, 0.f);
#pragma unroll
        for (int kq = 0; kq < 16; kq++) {
#pragma unroll
            for (int nn = 0; nn < 8; nn++) {
                float4 s4 = *(const float4*)(ls + (q * 8 + nn) * 64 + 4 * kq);
                ffma2(acc[nn], pk2(s4.x, s4.y), wl2[2 * kq]);
                ffma2(acc[nn], pk2(s4.z, s4.w), wl2[2 * kq + 1]);
            }
        }
#pragma unroll
        for (int nn = 0; nn < 8; nn++) {
            float2 f = upk2(acc[nn]);
            float r = fmaxf(f.x + f.y, 0.f);
            int node = n0 + q * 8 + nn;
            size_t iF = (((size_t)(2 * g)     * Bz + b) * Nn + node) * Ee + col;
            size_t iR = (((size_t)(2 * g + 1) * Bz + b) * Nn + node) * Ee + col;
            g_chA[iF] = r;  g_chA[iR] = r;
            __half rh = __float2half(r);
            g_whAh[iF] = rh; g_whAh[iR] = rh;
        }
    }
}

// ---------------- GRU input projection, 32 nodes/block -------------------
__global__ void __launch_bounds__(192)
k_xp(const float* __restrict__ S1, const float* __restrict__ S2,
     const float* __restrict__ K1, const float* __restrict__ K2,
     const float* __restrict__ B1, const float* __restrict__ B2)
{
    int g = blockIdx.z, b = blockIdx.y, n0 = blockIdx.x * 32;
    const float* S  = (g ? S2 : S1) + ((size_t)b * Nn + n0) * SEMD;
    const float* Wk = g ? K2 : K1;
    const float* bb = g ? B2 : B1;
    __shared__ __align__(16) float ss[32 * 64];
    int tid = threadIdx.x;                       // 192
    for (int idx = tid; idx < 32 * 64; idx += 192) ss[idx] = S[idx];
    int col = tid;
    ull wk2[32];
#pragma unroll
    for (int i = 0; i < 32; i++)
        wk2[i] = pk2(__ldg(&Wk[(2 * i) * G3H + col]), __ldg(&Wk[(2 * i + 1) * G3H + col]));
    float b0 = bb[col];
    __syncthreads();
    float* xp = g_xp + (((size_t)g * Bz + b) * Nn + n0) * G3H;
    for (int ngrp = 0; ngrp < 4; ngrp++) {
        ull acc[8];
#pragma unroll
        for (int nn = 0; nn < 8; nn++) acc[nn] = pk2(0.f, 0.f);
#pragma unroll
        for (int kq = 0; kq < 16; kq++) {
#pragma unroll
            for (int nn = 0; nn < 8; nn++) {
                float4 s4 = *(const float4*)(ss + (ngrp * 8 + nn) * 64 + 4 * kq);
                ffma2(acc[nn], pk2(s4.x, s4.y), wk2[2 * kq]);
                ffma2(acc[nn], pk2(s4.z, s4.w), wk2[2 * kq + 1]);
            }
        }
#pragma unroll
        for (int nn = 0; nn < 8; nn++) {
            float2 f = upk2(acc[nn]);
            xp[(size_t)(ngrp * 8 + nn) * G3H + col] = f.x + f.y + b0;
        }
    }
}

// ---------------- GRU scan ------------------------------------------------
__global__ void __launch_bounds__(192, 1)
k_gru(const float* __restrict__ rk1, const float* __restrict__ rk2,
      const float* __restrict__ gb1, const float* __restrict__ gb2)
{
    int g = blockIdx.x >> 5;
    int b = blockIdx.x & 31;
    const float* rk = g ? rk2 : rk1;
    const float* gb = g ? gb2 : gb1;
    __shared__ __align__(16) float sm[12288];
    int tid = threadIdx.x;                       // 192
    for (int idx = tid; idx < 64 * G3H; idx += 192) sm[idx] = rk[idx];
    __syncthreads();
    ull rk2p[32];
#pragma unroll
    for (int i = 0; i < 32; i++)
        rk2p[i] = pk2(sm[(2 * i) * G3H + tid], sm[(2 * i + 1) * G3H + tid]);
    __syncthreads();
    float* h_sh   = sm;
    float* pre_sh = sm + 64;
    float* rh_sh  = sm + 192;
    float* xh_sh  = sm + 256;
    if (tid < 64) h_sh[tid] = 0.f;
    float bb = gb[G3H + tid];
    const float* xp = g_xp + ((size_t)g * Bz + b) * Nn * G3H;
    size_t oF = (((size_t)(2 * g)     * Bz + b) * Nn) * Ee;
    size_t oR = (((size_t)(2 * g + 1) * Bz + b) * Nn) * Ee;
    __syncthreads();
    float xnext = xp[tid];
    for (int t = 0; t < Nn; t++) {
        float xv = xnext;
        if (t + 1 < Nn) xnext = xp[(size_t)(t + 1) * G3H + tid];
        ull a0 = pk2(0.f, 0.f), a1 = a0, a2 = a0, a3 = a0;
#pragma unroll
        for (int q = 0; q < 32; q += 4) {
            ffma2(a0, *(const ull*)(h_sh + 2 * q),     rk2p[q]);
            ffma2(a1, *(const ull*)(h_sh + 2 * q + 2), rk2p[q + 1]);
            ffma2(a2, *(const ull*)(h_sh + 2 * q + 4), rk2p[q + 2]);
            ffma2(a3, *(const ull*)(h_sh + 2 * q + 6), rk2p[q + 3]);
        }
        float2 f0 = upk2(a0), f1 = upk2(a1), f2 = upk2(a2), f3 = upk2(a3);
        float pre = ((f0.x + f0.y) + (f1.x + f1.y)) + ((f2.x + f2.y) + (f3.x + f3.y)) + bb;
        if (tid < 128) pre_sh[tid] = xv + pre;
        else { rh_sh[tid - 128] = pre; xh_sh[tid - 128] = xv; }
        __syncthreads();
        if (tid < 64) {
            float z = 1.f / (1.f + __expf(-pre_sh[tid]));
            float r = 1.f / (1.f + __expf(-pre_sh[64 + tid]));
            float ag = xh_sh[tid] + r * rh_sh[tid];
            ag = fminf(fmaxf(ag, -12.f), 12.f);
            float e2 = __expf(-2.f * ag);
            float hh = (1.f - e2) / (1.f + e2);
            float hn = z * h_sh[tid] + (1.f - z) * hh;
            h_sh[tid] = hn;
            float rl = fmaxf(hn, 0.f);
            size_t off = (size_t)t * Ee + 64 + tid;
            g_chA[oF + off] = rl;  g_chA[oR + off] = rl;
            __half rh16 = __float2half(rl);
            g_whAh[oF + off] = rh16;  g_whAh[oR + off] = rh16;
        }
        __syncthreads();
    }
}

// ---------------- per-step transform: tensor-core GEMM -------------------
// 256 threads / 8 warps, 64 nodes x 128 cols per block, wmma m16n16k16.
#define TLD 144
#define TR_SMEM ((64*TLD + 128*TLD) * 2)
__global__ void __launch_bounds__(256)
k_transform(int srcA,
            const float* __restrict__ a1w, const float* __restrict__ a1b,
            const float* __restrict__ a2w, const float* __restrict__ a2b)
{
    const __half* whh = srcA ? g_whAh : g_whBh;
    extern __shared__ __align__(16) __half dynh[];
    __half* A_sh = dynh;             // [64][TLD]
    __half* B_sh = dynh + 64 * TLD;  // [128][TLD]; reused as float C[64][128]
    __shared__ float av[256];
    int c = blockIdx.z, b = blockIdx.y, n0 = blockIdx.x * 64;
    size_t base = (((size_t)c * Bz + b) * Nn + n0) * Ee;
    int tid = threadIdx.x;
    if (tid < 128) av[tid] = a1w[tid];
    else           av[tid] = a2w[tid - 128];
    // stage A (wh fp16, 64x128) and B (Wg fp16, 128x128)
    {
        int row = tid >> 2, part = tid & 3;      // 64 rows x 4 parts x 32 halfs
        const uint4* src = (const uint4*)(whh + base) + row * 16 + part * 4;
        uint4* dst = (uint4*)(A_sh + row * TLD + part * 32);
#pragma unroll
        for (int i = 0; i < 4; i++) dst[i] = src[i];
    }
    {
        int row = tid >> 1, part = tid & 1;      // 128 rows x 2 parts x 64 halfs
        const uint4* src = (const uint4*)g_Wgh + row * 16 + part * 8;
        uint4* dst = (uint4*)(B_sh + row * TLD + part * 64);
#pragma unroll
        for (int i = 0; i < 8; i++) dst[i] = src[i];
    }
    __syncthreads();

    int w = tid >> 5, lane = tid & 31;
    int mt = w >> 1, ct0 = (w & 1) * 4;          // node tile, col tile base
    wmma::fragment<wmma::accumulator, 16, 16, 16, float> acc[4];
#pragma unroll
    for (int j = 0; j < 4; j++) wmma::fill_fragment(acc[j], 0.f);
#pragma unroll
    for (int k = 0; k < 8; k++) {
        wmma::fragment<wmma::matrix_a, 16, 16, 16, __half, wmma::row_major> fa;
        wmma::load_matrix_sync(fa, A_sh + (mt * 16) * TLD + k * 16, TLD);
#pragma unroll
        for (int j = 0; j < 4; j++) {
            wmma::fragment<wmma::matrix_b, 16, 16, 16, __half, wmma::row_major> fb;
            wmma::load_matrix_sync(fb, B_sh + (k * 16) * TLD + (ct0 + j) * 16, TLD);
            wmma::mma_sync(acc[j], fa, fb, acc[j]);
        }
    }
    __syncthreads();                              // all B reads done
    float* Cf = (float*)B_sh;
#pragma unroll
    for (int j = 0; j < 4; j++)
        wmma::store_matrix_sync(Cf + (mt * 16) * 128 + (ct0 + j) * 16, acc[j],
                                128, wmma::mem_row_major);
    __syncthreads();
    // convert C -> ghw fp16
    {
        const float2* c2 = (const float2*)Cf;
        __half2* d2 = (__half2*)(g_ghwh + base);
        for (int i = tid; i < 64 * 128 / 2; i += 256)
            d2[i] = __float22half2_rn(c2[i]);
    }
    // attention projections: 8 warps x 8 nodes (from fp16 wh)
#pragma unroll
    for (int ii = 0; ii < 8; ii++) {
        int node = w * 8 + ii;
        float x0 = __half2float(A_sh[node * TLD + lane]);
        float x1 = __half2float(A_sh[node * TLD + 64 + lane]);
        float s1 = x0 * av[lane]       + x1 * av[64 + lane];
        float s2 = x0 * av[128 + lane] + x1 * av[192 + lane];
#pragma unroll
        for (int off = 16; off; off >>= 1) {
            s1 += __shfl_xor_sync(0xffffffffu, s1, off);
            s2 += __shfl_xor_sync(0xffffffffu, s2, off);
        }
        if (lane == 0) {
            size_t idx = ((size_t)c * Bz + b) * Nn + n0 + node;
            g_ah1[idx] = s1 + a1b[0];
            g_ah2[idx] = s2 + a2b[0];
        }
    }
}

// ---------------- per-step attend: ghw staged in smem (fp16) -------------
// Two blocks per (c,b) (node halves); 1024 threads = 32 warps x 8 nodes.
#define ATT_SMEM (512*128*2 + 32*128*4 + 32*128*2)
__global__ void __launch_bounds__(1024)
k_attend(int srcA)
{
    const float* whc = srcA ? g_chA : g_chB;
    float*       whn = srcA ? g_chB : g_chA;
    __half*      whnh = srcA ? g_whBh : g_whAh;
    int c = blockIdx.y, b = blockIdx.x, half = blockIdx.z;
    size_t cb = ((size_t)c * Bz + b) * Nn;
    extern __shared__ __align__(16) char dyn[];
    __half* ghw_sh = (__half*)dyn;
    float*  p_all  = (float*)(dyn + 512 * 128 * 2);
    short*  nj_all = (short*)(dyn + 512 * 128 * 2 + 32 * 128 * 4);
    int tid = threadIdx.x, lane = tid & 31, w = tid >> 5;

    {
        const uint4* src = (const uint4*)(g_ghwh + cb * Ee);
        uint4* dst = (uint4*)ghw_sh;
        for (int idx = tid; idx < 512 * 128 * 2 / 16; idx += 1024) dst[idx] = src[idx];
    }
    __syncthreads();

    float* p_w  = p_all  + w * MAXD;
    short* nj_w = nj_all + w * MAXD;
    const uint2* gptr = (const uint2*)ghw_sh;

    for (int ii = 0; ii < 8; ii++) {
        int i = half * 256 + w * 8 + ii;
        int cnt = g_cnt[cb + i];
        float ah1i = g_ah1[cb + i];
        const short* adjr = g_adj + (cb + i) * MAXD;
        float e[4]; short njr[4];
#pragma unroll
        for (int q = 0; q < 4; q++) {
            int idx = lane + 32 * q;
            if (idx < cnt) {
                njr[q] = adjr[idx];
                float x = ah1i + g_ah2[cb + njr[q]];
                e[q] = x > 0.f ? x : 0.2f * x;
            } else { e[q] = -3.0e38f; njr[q] = 0; }
        }
        float m = fmaxf(fmaxf(e[0], e[1]), fmaxf(e[2], e[3]));
#pragma unroll
        for (int off = 16; off; off >>= 1)
            m = fmaxf(m, __shfl_xor_sync(0xffffffffu, m, off));
        float p[4]; float s = 0.f;
#pragma unroll
        for (int q = 0; q < 4; q++) {
            p[q] = (lane + 32 * q < cnt) ? __expf(e[q] - m) : 0.f;
            s += p[q];
        }
#pragma unroll
        for (int off = 16; off; off >>= 1)
            s += __shfl_xor_sync(0xffffffffu, s, off);
        float inv = cnt > 0 ? 1.f / s : 0.f;
#pragma unroll
        for (int q = 0; q < 4; q++) {
            p_w[lane + 32 * q]  = p[q] * inv;
            nj_w[lane + 32 * q] = njr[q];
        }
        __syncwarp();
        float4 acc = make_float4(0.f, 0.f, 0.f, 0.f);
#pragma unroll 2
        for (int j = 0; j < cnt; j++) {
            int nj = nj_w[j];
            float pj = p_w[j];
            uint2 hv = gptr[nj * 32 + lane];
            float2 f01 = __half22float2(*reinterpret_cast<__half2*>(&hv.x));
            float2 f23 = __half22float2(*reinterpret_cast<__half2*>(&hv.y));
            acc.x = fmaf(pj, f01.x, acc.x);
            acc.y = fmaf(pj, f01.y, acc.y);
            acc.z = fmaf(pj, f23.x, acc.z);
            acc.w = fmaf(pj, f23.y, acc.w);
        }
        float4 wc = *(const float4*)(whc + (cb + i) * Ee + 4 * lane);
        float4 v;
        v.x = wc.x + acc.x; v.y = wc.y + acc.y;
        v.z = wc.z + acc.z; v.w = wc.w + acc.w;
        v.x = v.x > 0.f ? v.x : expm1f(v.x);
        v.y = v.y > 0.f ? v.y : expm1f(v.y);
        v.z = v.z > 0.f ? v.z : expm1f(v.z);
        v.w = v.w > 0.f ? v.w : expm1f(v.w);
        *(float4*)(whn + (cb + i) * Ee + 4 * lane) = v;
        union { __half2 h[2]; uint2 u; } cv;
        cv.h[0] = __float22half2_rn(make_float2(v.x, v.y));
        cv.h[1] = __float22half2_rn(make_float2(v.z, v.w));
        *(uint2*)(whnh + (cb + i) * Ee + 4 * lane) = cv.u;
        __syncwarp();
    }
}

// ---------------- sum over nodes + output projection ---------------------
__global__ void k_reduce(const float* __restrict__ Wout,
                         const float* __restrict__ bout)
{
    int b = blockIdx.x, g = blockIdx.y;
    int tid = threadIdx.x;                       // 128
    __shared__ float mid[128];
    const float* f = g_chB + ((size_t)(2 * g)     * Bz + b) * Nn * Ee;
    const float* r = g_chB + ((size_t)(2 * g + 1) * Bz + b) * Nn * Ee;
    float s = 0.f;
#pragma unroll 4
    for (int n = 0; n < Nn; n++)
        s += f[(size_t)n * Ee + tid] + r[(size_t)n * Ee + tid];
    mid[tid] = s;
    __syncthreads();
    if (tid < OUTD) {
        float acc = bout[tid];
#pragma unroll 8
        for (int e = 0; e < Ee; e++)
            acc = fmaf(mid[e], __ldg(&Wout[e * OUTD + tid]), acc);
        g_emb[((size_t)g * Bz + b) * OUTD + tid] = acc;
    }
}

// ---------------- cosine similarity -> (1+cos)/2 -------------------------
__global__ void k_cos(float* __restrict__ out)
{
    int b = blockIdx.x;
    int tid = threadIdx.x, lane = tid & 31, w = tid >> 5;
    float x1 = g_emb[(size_t)b * OUTD + tid];
    float x2 = g_emb[(size_t)(Bz + b) * OUTD + tid];
    float d = x1 * x2, n1 = x1 * x1, n2 = x2 * x2;
#pragma unroll
    for (int off = 16; off; off >>= 1) {
        d  += __shfl_xor_sync(0xffffffffu, d,  off);
        n1 += __shfl_xor_sync(0xffffffffu, n1, off);
        n2 += __shfl_xor_sync(0xffffffffu, n2, off);
    }
    __shared__ float sh[6];
    if (lane == 0) { sh[w * 3] = d; sh[w * 3 + 1] = n1; sh[w * 3 + 2] = n2; }
    __syncthreads();
    if (tid == 0) {
        float dd = sh[0] + sh[3], a = sh[1] + sh[4], c2 = sh[2] + sh[5];
        float denom = fmaxf(sqrtf(a), 1e-12f) * fmaxf(sqrtf(c2), 1e-12f);
        out[b] = 0.5f * (1.f + dd / denom);
    }
}

// ---------------- launch sequence ----------------------------------------
extern "C" void kernel_launch(void* const* d_in, const int* in_sizes, int n_in,
                              void* d_out, int out_size)
{
    const float* CFG1 = (const float*)d_in[0];
    const float* LIT1 = (const float*)d_in[2];
    const float* SEM1 = (const float*)d_in[3];
    const float* CFG2 = (const float*)d_in[4];
    const float* LIT2 = (const float*)d_in[6];
    const float* SEM2 = (const float*)d_in[7];
    const float* Wl1  = (const float*)d_in[8];
    const float* gk1  = (const float*)d_in[9];
    const float* grk1 = (const float*)d_in[10];
    const float* gb1  = (const float*)d_in[11];
    const float* Wl2  = (const float*)d_in[12];
    const float* gk2  = (const float*)d_in[13];
    const float* grk2 = (const float*)d_in[14];
    const float* gb2  = (const float*)d_in[15];
    const float* a1w  = (const float*)d_in[16];
    const float* a1b  = (const float*)d_in[17];
    const float* a2w  = (const float*)d_in[18];
    const float* a2b  = (const float*)d_in[19];
    const float* Wg   = (const float*)d_in[20];
    const float* Wout = (const float*)d_in[21];
    const float* bout = (const float*)d_in[22];

    cudaFuncSetAttribute(k_transform, cudaFuncAttributeMaxDynamicSharedMemorySize, TR_SMEM);
    cudaFuncSetAttribute(k_attend,    cudaFuncAttributeMaxDynamicSharedMemorySize, ATT_SMEM);

    k_prep<<<16, 1024>>>(Wg);
    k_build_fwd<<<dim3(64, 32, 2), 256>>>(CFG1, CFG2);
    k_build_rev<<<dim3(2, 32, 2), 256>>>(CFG1, CFG2);
    k_lit<<<dim3(16, 32, 2), 256>>>(LIT1, LIT2, Wl1, Wl2);
    k_xp <<<dim3(16, 32, 2), 192>>>(SEM1, SEM2, gk1, gk2, gb1, gb2);
    k_gru<<<64, 192>>>(grk1, grk2, gb1, gb2);

    int srcA = 1;
    for (int s = 0; s < 3; s++) {
        k_transform<<<dim3(8, 32, 4), 256, TR_SMEM>>>(srcA, a1w, a1b, a2w, a2b);
        k_attend   <<<dim3(32, 4, 2), 1024, ATT_SMEM>>>(srcA);
        srcA ^= 1;
    }
    k_reduce<<<dim3(32, 2), 128>>>(Wout, bout);
    k_cos<<<32, 64>>>((float*)d_out);
}